// round 5
// baseline (speedup 1.0000x reference)
#include <cuda_runtime.h>

// RowLSTM: B=16, Cin=64, H=W=64, HID=128, K=3 (causal mask kills k=2 tap on input conv)
#define BB   16
#define CIN  64
#define HID  128
#define HH   64
#define WW   64

// ---------------- device scratch (no runtime allocation allowed) ----------------
// z_is buffer: [row][b][j][gate][w]  (gate order: i, f, o, g)
__device__ float g_zbuf[(size_t)HH * BB * HID * 4 * WW];   // 128 MB
__device__ __align__(16) float g_hbuf[2][BB * HID * WW];   // h ping-pong (L2 exchange)
// transposed weights: gates contiguous so a 64-bit load covers a gate-pair of channel j
__device__ float g_Wx[CIN * 2 * HID * 4];   // [(ci*2+k)][j][g], k in {0,1} (tap2 masked)
__device__ float g_Wh[HID * 3 * HID * 4];   // [(cj*3+k)][j][g]
__device__ float g_bias[HID * 4];           // b_is + b_ss, [j][g]
// per-batch monotonic ticket barrier; zeroed by prep_kernel each launch.
// 64-int stride (256 B) between batches to avoid L2-hash line pairing.
__device__ int g_cnt[BB * 64];

// ---------------- packed f32x2 helpers ----------------
typedef unsigned long long u64;

__device__ __forceinline__ void fma2(u64& acc, u64 a, u64 b) {
    asm("fma.rn.f32x2 %0, %1, %2, %0;" : "+l"(acc) : "l"(a), "l"(b));
}
__device__ __forceinline__ u64 dup2(float v) {
    u64 r;
    asm("mov.b64 %0, {%1, %1};" : "=l"(r) : "f"(v));
    return r;
}
__device__ __forceinline__ u64 pack2(float lo, float hi) {
    u64 r;
    asm("mov.b64 %0, {%1, %2};" : "=l"(r) : "f"(lo), "f"(hi));
    return r;
}
__device__ __forceinline__ void unpack2(float& lo, float& hi, u64 v) {
    asm("mov.b64 {%0, %1}, %2;" : "=f"(lo), "=f"(hi) : "l"(v));
}

// ---------------- scalar helpers ----------------
__device__ __forceinline__ float sigm(float z) {
    return 1.0f / (1.0f + __expf(-z));
}
__device__ __forceinline__ float tanh_f(float z) {
    // accurate + overflow-safe: tanh(|z|) = (1-e^{-2|z|})/(1+e^{-2|z|})
    float e = __expf(-2.0f * fabsf(z));
    float t = (1.0f - e) / (1.0f + e);
    return (z >= 0.0f) ? t : -t;
}

// per-batch 8-CTA ticket barrier, round = row+1.
// All 128 CTAs are co-resident (grid 128 < 148 SMs, single wave) -> spin is safe.
// Monotonic within a launch; prep_kernel zeroes g_cnt at the start of every
// launch, so behavior is identical across graph replays.
__device__ __forceinline__ void batch_barrier(int b, int round) {
    __syncthreads();
    if (threadIdx.x == 0) {
        const int s = b * 64;
        __threadfence();                       // release: h stores -> L2 before arrive
        atomicAdd(&g_cnt[s], 1);
        const int target = 8 * round;
        while (*(volatile int*)&g_cnt[s] < target) { }
        __threadfence();                       // acquire: h loads after all arrivals
    }
    __syncthreads();
}

// ---------------- prep: weight transpose + bias fuse + barrier reset ----------------
__global__ void prep_kernel(const float* __restrict__ w_is, const float* __restrict__ b_is,
                            const float* __restrict__ w_ss, const float* __restrict__ b_ss) {
    int tid = blockIdx.x * blockDim.x + threadIdx.x;
    // g_Wx: idx = ((ci*2+k)*HID + j)*4 + g = ck*512 + j*4 + g
    if (tid < CIN * 2 * HID * 4) {
        int g = tid & 3, j = (tid >> 2) & 127, ck = tid >> 9;
        int k = ck & 1, ci = ck >> 1;
        g_Wx[tid] = w_is[((g * HID + j) * CIN + ci) * 3 + k];   // w_is[o][ci][0][k]
    }
    // g_Wh: idx = ((cj*3+k)*HID + j)*4 + g
    if (tid < HID * 3 * HID * 4) {
        int g = tid & 3, j = (tid >> 2) & 127, ck = tid >> 9;
        int k = ck % 3, cj = ck / 3;
        g_Wh[tid] = w_ss[((g * HID + j) * HID + cj) * 3 + k];   // w_ss[o][cj][0][k]
    }
    if (tid < HID * 4) {
        int g = tid & 3, j = tid >> 2;
        g_bias[tid] = b_is[g * HID + j] + b_ss[g * HID + j];
    }
    if (tid < BB * 64) g_cnt[tid] = 0;         // reset ticket barrier every launch
}

// ---------------- input-to-state conv: z_is for all rows ----------------
// grid (8 jgroups, 16 b, 64 rows), 256 threads; CTA tile: 16 j x 4 gates x 64 w
// per-thread tile: 1 j x 4 gates x 4 w, packed as (i,f)/(o,g) f32x2 pairs
__global__ __launch_bounds__(256) void zis_kernel(const float* __restrict__ x) {
    const int jg = blockIdx.x, b = blockIdx.y, row = blockIdx.z;
    __shared__ __align__(16) float xs[CIN][68];  // xs[ci][w+1]=x[..w]; [0] = left pad
    const int t = threadIdx.x;

    // vectorized row load: x row is 16B-aligned (WW*4 = 256B row stride)
    {
        const float4* __restrict__ xrow4 =
            (const float4*)&x[((size_t)(b * CIN) * HH + row) * WW];
        // ci-th row of x at offset ci*HH*WW/4 float4s from xrow4
        for (int i = t; i < CIN * (WW / 4); i += 256) {
            int ci = i >> 4, v = i & 15;                 // 16 float4 per row
            float4 q = xrow4[(size_t)ci * (HH * WW / 4) + v];
            float* d = &xs[ci][v * 4 + 1];
            d[0] = q.x; d[1] = q.y; d[2] = q.z; d[3] = q.w;
        }
    }
    if (t < CIN) xs[t][0] = 0.0f;
    __syncthreads();

    const int tw = t & 15, tj = t >> 4;
    const int j = jg * 16 + tj;
    const int w0 = tw * 4;

    float4 bias4 = *(const float4*)&g_bias[j * 4];
    u64 bIF = pack2(bias4.x, bias4.y);
    u64 bOG = pack2(bias4.z, bias4.w);
    u64 aIF0 = bIF, aIF1 = bIF, aIF2 = bIF, aIF3 = bIF;
    u64 aOG0 = bOG, aOG1 = bOG, aOG2 = bOG, aOG3 = bOG;

    const ulonglong2* __restrict__ Wx2 = (const ulonglong2*)g_Wx;
#pragma unroll 4
    for (int ci = 0; ci < CIN; ci++) {
        ulonglong2 wk0 = Wx2[(ci * 2 + 0) * HID + j];   // .x=(wi,wf), .y=(wo,wg), tap w-1
        ulonglong2 wk1 = Wx2[(ci * 2 + 1) * HID + j];   // tap w
        float4 v4 = *(const float4*)&xs[ci][w0];        // x[w0-1 .. w0+2]
        float  ve = xs[ci][w0 + 4];                     // x[w0+3]
        u64 s0 = dup2(v4.x), s1 = dup2(v4.y), s2 = dup2(v4.z), s3 = dup2(v4.w), s4 = dup2(ve);
        fma2(aIF0, wk0.x, s0); fma2(aIF0, wk1.x, s1);
        fma2(aOG0, wk0.y, s0); fma2(aOG0, wk1.y, s1);
        fma2(aIF1, wk0.x, s1); fma2(aIF1, wk1.x, s2);
        fma2(aOG1, wk0.y, s1); fma2(aOG1, wk1.y, s2);
        fma2(aIF2, wk0.x, s2); fma2(aIF2, wk1.x, s3);
        fma2(aOG2, wk0.y, s2); fma2(aOG2, wk1.y, s3);
        fma2(aIF3, wk0.x, s3); fma2(aIF3, wk1.x, s4);
        fma2(aOG3, wk0.y, s3); fma2(aOG3, wk1.y, s4);
    }

    float zi0, zf0, zi1, zf1, zi2, zf2, zi3, zf3;
    float zo0, zg0, zo1, zg1, zo2, zg2, zo3, zg3;
    unpack2(zi0, zf0, aIF0); unpack2(zi1, zf1, aIF1);
    unpack2(zi2, zf2, aIF2); unpack2(zi3, zf3, aIF3);
    unpack2(zo0, zg0, aOG0); unpack2(zo1, zg1, aOG1);
    unpack2(zo2, zg2, aOG2); unpack2(zo3, zg3, aOG3);

    // store gate-major: [row][b][j][g][w0..w0+3] (write-only -> bypass L1)
    size_t base = ((size_t)((row * BB + b) * HID + j)) * 4 * WW + w0;
    __stcg((float4*)&g_zbuf[base + 0 * WW], make_float4(zi0, zi1, zi2, zi3));
    __stcg((float4*)&g_zbuf[base + 1 * WW], make_float4(zf0, zf1, zf2, zf3));
    __stcg((float4*)&g_zbuf[base + 2 * WW], make_float4(zo0, zo1, zo2, zo3));
    __stcg((float4*)&g_zbuf[base + 3 * WW], make_float4(zg0, zg1, zg2, zg3));
}

// ---------------- persistent recurrence: all 64 rows in one kernel ----------------
// grid (8 jgroups, 16 b), 256 threads; thread tile: 1 j x 4 gates x 4 w
// c lives in registers for all rows; h exchanged through L2 (stcg/ldcg ping-pong)
// with a per-batch 8-CTA ticket barrier between rows. z for the next row is
// prefetched before each row's FFMA loop so its HBM latency is hidden.
__global__ __launch_bounds__(256) void steps_kernel(float* __restrict__ out) {
    const int jg = blockIdx.x, b = blockIdx.y;
    __shared__ __align__(16) float hs[HID][68];  // hs[cj][w+1]=h[cj][w]; [0],[65] pads
    const int t = threadIdx.x;

    // h_{-1} = 0 (also sets pads, which stay zero forever)
    for (int i = t; i < HID * 68; i += 256) ((float*)hs)[i] = 0.0f;
    __syncthreads();

    const int tw = t & 15, tj = t >> 4;
    const int j = jg * 16 + tj;
    const int w0 = tw * 4;
    const int hbase = (b * HID + j) * WW + w0;
    const size_t zstride = (size_t)BB * HID * 4 * WW;          // per-row stride
    const float* zp = &g_zbuf[((size_t)(b * HID + j)) * 4 * WW + w0];

    float4 c4 = make_float4(0.0f, 0.0f, 0.0f, 0.0f);           // cell state in registers
    const ulonglong2* __restrict__ Wh2 = (const ulonglong2*)g_Wh;

    // z for row 0
    float4 qi = __ldcg((const float4*)&zp[0 * WW]);
    float4 qf = __ldcg((const float4*)&zp[1 * WW]);
    float4 qo = __ldcg((const float4*)&zp[2 * WW]);
    float4 qg = __ldcg((const float4*)&zp[3 * WW]);

    for (int row = 0; row < HH; row++) {
        // accumulators from prefetched z (bias already folded in)
        u64 aIF0 = pack2(qi.x, qf.x), aIF1 = pack2(qi.y, qf.y);
        u64 aIF2 = pack2(qi.z, qf.z), aIF3 = pack2(qi.w, qf.w);
        u64 aOG0 = pack2(qo.x, qg.x), aOG1 = pack2(qo.y, qg.y);
        u64 aOG2 = pack2(qo.z, qg.z), aOG3 = pack2(qo.w, qg.w);

        // prefetch z for next row: hidden under the 128-iteration FFMA loop
        if (row + 1 < HH) {
            const float* znext = zp + (size_t)(row + 1) * zstride;
            qi = __ldcg((const float4*)&znext[0 * WW]);
            qf = __ldcg((const float4*)&znext[1 * WW]);
            qo = __ldcg((const float4*)&znext[2 * WW]);
            qg = __ldcg((const float4*)&znext[3 * WW]);
        }

#pragma unroll 2
        for (int cj = 0; cj < HID; cj++) {
            ulonglong2 wk0 = Wh2[(cj * 3 + 0) * HID + j];   // .x=(wi,wf), .y=(wo,wg)
            ulonglong2 wk1 = Wh2[(cj * 3 + 1) * HID + j];
            ulonglong2 wk2 = Wh2[(cj * 3 + 2) * HID + j];
            float4 v4 = *(const float4*)&hs[cj][w0];        // h[w0-1 .. w0+2]
            float  ve = hs[cj][w0 + 4];                     // h[w0+3]
            float  v5 = hs[cj][w0 + 5];                     // h[w0+4] (zero at right edge)
            u64 s0 = dup2(v4.x), s1 = dup2(v4.y), s2 = dup2(v4.z);
            u64 s3 = dup2(v4.w), s4 = dup2(ve),  s5 = dup2(v5);
            fma2(aIF0, wk0.x, s0); fma2(aIF0, wk1.x, s1); fma2(aIF0, wk2.x, s2);
            fma2(aOG0, wk0.y, s0); fma2(aOG0, wk1.y, s1); fma2(aOG0, wk2.y, s2);
            fma2(aIF1, wk0.x, s1); fma2(aIF1, wk1.x, s2); fma2(aIF1, wk2.x, s3);
            fma2(aOG1, wk0.y, s1); fma2(aOG1, wk1.y, s2); fma2(aOG1, wk2.y, s3);
            fma2(aIF2, wk0.x, s2); fma2(aIF2, wk1.x, s3); fma2(aIF2, wk2.x, s4);
            fma2(aOG2, wk0.y, s2); fma2(aOG2, wk1.y, s3); fma2(aOG2, wk2.y, s4);
            fma2(aIF3, wk0.x, s3); fma2(aIF3, wk1.x, s4); fma2(aIF3, wk2.x, s5);
            fma2(aOG3, wk0.y, s3); fma2(aOG3, wk1.y, s4); fma2(aOG3, wk2.y, s5);
        }

        float4 hnew;
        {
            float zi, zf, zo, zg;
            unpack2(zi, zf, aIF0); unpack2(zo, zg, aOG0);
            float ig = sigm(zi), fg = sigm(zf), og = sigm(zo), gg = tanh_f(zg);
            c4.x = fg * c4.x + ig * gg;  hnew.x = og * tanh_f(c4.x);
        }
        {
            float zi, zf, zo, zg;
            unpack2(zi, zf, aIF1); unpack2(zo, zg, aOG1);
            float ig = sigm(zi), fg = sigm(zf), og = sigm(zo), gg = tanh_f(zg);
            c4.y = fg * c4.y + ig * gg;  hnew.y = og * tanh_f(c4.y);
        }
        {
            float zi, zf, zo, zg;
            unpack2(zi, zf, aIF2); unpack2(zo, zg, aOG2);
            float ig = sigm(zi), fg = sigm(zf), og = sigm(zo), gg = tanh_f(zg);
            c4.z = fg * c4.z + ig * gg;  hnew.z = og * tanh_f(c4.z);
        }
        {
            float zi, zf, zo, zg;
            unpack2(zi, zf, aIF3); unpack2(zo, zg, aOG3);
            float ig = sigm(zi), fg = sigm(zf), og = sigm(zo), gg = tanh_f(zg);
            c4.w = fg * c4.w + ig * gg;  hnew.w = og * tanh_f(c4.w);
        }

        // publish h (L2, bypass L1) + final output (write-only -> bypass L1)
        float* hb = g_hbuf[row & 1];
        __stcg((float4*)&hb[hbase], hnew);
        __stcg((float4*)&out[((size_t)(b * HID + j) * HH + row) * WW + w0], hnew);

        // all 8 CTAs of this batch sync, then reload full h row into smem
        batch_barrier(b, row + 1);

        if (row + 1 < HH) {
            // vectorized L2 read: 8 x LDG.128 per thread instead of 32 x LDG.32
            const float4* __restrict__ hbr4 =
                (const float4*)&g_hbuf[row & 1][(size_t)b * HID * WW];
            for (int i = t; i < HID * (WW / 4); i += 256) {
                int cj = i >> 4, v = i & 15;             // 16 float4 per cj row
                float4 q = __ldcg(&hbr4[i]);
                float* d = &hs[cj][v * 4 + 1];
                d[0] = q.x; d[1] = q.y; d[2] = q.z; d[3] = q.w;
            }
            __syncthreads();
        }
    }
}

// ---------------- launch ----------------
extern "C" void kernel_launch(void* const* d_in, const int* in_sizes, int n_in,
                              void* d_out, int out_size) {
    // robust input identification by element count
    const float* x = nullptr;
    const float* w_is = nullptr;
    const float* b_is = nullptr;
    const float* w_ss = nullptr;
    const float* b_ss = nullptr;
    for (int i = 0; i < n_in; i++) {
        int sz = in_sizes[i];
        const float* p = (const float*)d_in[i];
        if (sz == BB * CIN * HH * WW)            x = p;       // 4,194,304
        else if (sz == 4 * HID * CIN * 3)        w_is = p;    // 98,304
        else if (sz == 4 * HID * HID * 3)        w_ss = p;    // 196,608
        else if (sz == 4 * HID) {                             // 512 (b_is first, b_ss second)
            if (!b_is) b_is = p; else b_ss = p;
        }
    }
    float* out = (float*)d_out;

    prep_kernel<<<768, 256>>>(w_is, b_is, w_ss, b_ss);
    zis_kernel<<<dim3(8, BB, HH), 256>>>(x);
    steps_kernel<<<dim3(8, BB), 256>>>(out);   // 128 CTAs: single wave, co-resident
}

// round 10
// speedup vs baseline: 2.9012x; 2.9012x over previous
#include <cuda_runtime.h>

// RowLSTM: B=16, Cin=64, H=W=64, HID=128, K=3 (causal mask kills k=2 tap on input conv)
#define BB   16
#define CIN  64
#define HID  128
#define HH   64
#define WW   64

// dynamic smem for steps_kernel: hs[128][68] floats + Wh slice (384 rows x 16 j x 16B)
#define SMEM_HS_FLOATS   (HID * 68)                  // 8704 floats = 34816 B
#define SMEM_WS_BYTES    (HID * 3 * 16 * 16)         // 384*16 ulonglong2 = 98304 B
#define SMEM_STEPS_BYTES (SMEM_HS_FLOATS * 4 + SMEM_WS_BYTES)   // 133120 B

// ---------------- device scratch (no runtime allocation allowed) ----------------
// z_is buffer: [row][b][j][gate][w]  (gate order: i, f, o, g)
__device__ __align__(16) float g_zbuf[(size_t)HH * BB * HID * 4 * WW];   // 128 MB
__device__ __align__(16) float g_hbuf[2][BB * HID * WW];   // h ping-pong (L2 exchange)
// transposed weights: gates contiguous so a 64-bit load covers a gate-pair of channel j
__device__ __align__(16) float g_Wx[CIN * 2 * HID * 4];   // [(ci*2+k)][j][g]
__device__ __align__(16) float g_Wh[HID * 3 * HID * 4];   // [(cj*3+k)][j][g]
__device__ __align__(16) float g_bias[HID * 4];           // b_is + b_ss, [j][g]
// per-batch monotonic ticket barrier; zeroed by prep_kernel each launch.
// 64-int stride (256 B) between batches to avoid L2-hash line pairing.
__device__ int g_cnt[BB * 64];

// ---------------- packed f32x2 helpers ----------------
typedef unsigned long long u64;

__device__ __forceinline__ void fma2(u64& acc, u64 a, u64 b) {
    asm("fma.rn.f32x2 %0, %1, %2, %0;" : "+l"(acc) : "l"(a), "l"(b));
}
__device__ __forceinline__ u64 dup2(float v) {
    u64 r;
    asm("mov.b64 %0, {%1, %1};" : "=l"(r) : "f"(v));
    return r;
}
__device__ __forceinline__ u64 pack2(float lo, float hi) {
    u64 r;
    asm("mov.b64 %0, {%1, %2};" : "=l"(r) : "f"(lo), "f"(hi));
    return r;
}
__device__ __forceinline__ void unpack2(float& lo, float& hi, u64 v) {
    asm("mov.b64 {%0, %1}, %2;" : "=f"(lo), "=f"(hi) : "l"(v));
}

// ---------------- scalar helpers ----------------
__device__ __forceinline__ float sigm(float z) {
    return 1.0f / (1.0f + __expf(-z));
}
__device__ __forceinline__ float tanh_f(float z) {
    // accurate + overflow-safe: tanh(|z|) = (1-e^{-2|z|})/(1+e^{-2|z|})
    float e = __expf(-2.0f * fabsf(z));
    float t = (1.0f - e) / (1.0f + e);
    return (z >= 0.0f) ? t : -t;
}

// per-batch 8-CTA ticket barrier, round = row+1.
// All 128 CTAs are co-resident (grid 128 < 148 SMs, single wave) -> spin is safe.
__device__ __forceinline__ void batch_barrier(int b, int round) {
    __syncthreads();
    if (threadIdx.x == 0) {
        const int s = b * 64;
        __threadfence();                       // release: h stores -> L2 before arrive
        atomicAdd(&g_cnt[s], 1);
        const int target = 8 * round;
        while (*(volatile int*)&g_cnt[s] < target) {
            __nanosleep(128);                  // back off: don't hammer the L2 line
        }
        __threadfence();                       // acquire: h loads after all arrivals
    }
    __syncthreads();
}

// ---------------- prep: weight transpose + bias fuse + barrier reset ----------------
__global__ void prep_kernel(const float* __restrict__ w_is, const float* __restrict__ b_is,
                            const float* __restrict__ w_ss, const float* __restrict__ b_ss) {
    int tid = blockIdx.x * blockDim.x + threadIdx.x;
    // g_Wx: idx = ((ci*2+k)*HID + j)*4 + g = ck*512 + j*4 + g
    if (tid < CIN * 2 * HID * 4) {
        int g = tid & 3, j = (tid >> 2) & 127, ck = tid >> 9;
        int k = ck & 1, ci = ck >> 1;
        g_Wx[tid] = w_is[((g * HID + j) * CIN + ci) * 3 + k];   // w_is[o][ci][0][k]
    }
    // g_Wh: idx = ((cj*3+k)*HID + j)*4 + g
    if (tid < HID * 3 * HID * 4) {
        int g = tid & 3, j = (tid >> 2) & 127, ck = tid >> 9;
        int k = ck % 3, cj = ck / 3;
        g_Wh[tid] = w_ss[((g * HID + j) * HID + cj) * 3 + k];   // w_ss[o][cj][0][k]
    }
    if (tid < HID * 4) {
        int g = tid & 3, j = tid >> 2;
        g_bias[tid] = b_is[g * HID + j] + b_ss[g * HID + j];
    }
    if (tid < BB * 64) g_cnt[tid] = 0;         // reset ticket barrier every launch
}

// ---------------- input-to-state conv: z_is for all rows ----------------
// grid (8 jgroups, 16 b, 64 rows), 256 threads; CTA tile: 16 j x 4 gates x 64 w
__global__ __launch_bounds__(256) void zis_kernel(const float* __restrict__ x) {
    const int jg = blockIdx.x, b = blockIdx.y, row = blockIdx.z;
    __shared__ __align__(16) float xs[CIN][68];  // xs[ci][w+1]=x[..w]; [0] = left pad
    const int t = threadIdx.x;

    // vectorized row load: x row is 16B-aligned (WW*4 = 256B row stride)
    {
        const float4* __restrict__ xrow4 =
            (const float4*)&x[((size_t)(b * CIN) * HH + row) * WW];
        for (int i = t; i < CIN * (WW / 4); i += 256) {
            int ci = i >> 4, v = i & 15;                 // 16 float4 per row
            float4 q = xrow4[(size_t)ci * (HH * WW / 4) + v];
            float* d = &xs[ci][v * 4 + 1];
            d[0] = q.x; d[1] = q.y; d[2] = q.z; d[3] = q.w;
        }
    }
    if (t < CIN) xs[t][0] = 0.0f;
    __syncthreads();

    const int tw = t & 15, tj = t >> 4;
    const int j = jg * 16 + tj;
    const int w0 = tw * 4;

    float4 bias4 = *(const float4*)&g_bias[j * 4];
    u64 bIF = pack2(bias4.x, bias4.y);
    u64 bOG = pack2(bias4.z, bias4.w);
    u64 aIF0 = bIF, aIF1 = bIF, aIF2 = bIF, aIF3 = bIF;
    u64 aOG0 = bOG, aOG1 = bOG, aOG2 = bOG, aOG3 = bOG;

    const ulonglong2* __restrict__ Wx2 = (const ulonglong2*)g_Wx;
#pragma unroll 4
    for (int ci = 0; ci < CIN; ci++) {
        ulonglong2 wk0 = Wx2[(ci * 2 + 0) * HID + j];   // .x=(wi,wf), .y=(wo,wg), tap w-1
        ulonglong2 wk1 = Wx2[(ci * 2 + 1) * HID + j];   // tap w
        float4 v4 = *(const float4*)&xs[ci][w0];        // x[w0-1 .. w0+2]
        float  ve = xs[ci][w0 + 4];                     // x[w0+3]
        u64 s0 = dup2(v4.x), s1 = dup2(v4.y), s2 = dup2(v4.z), s3 = dup2(v4.w), s4 = dup2(ve);
        // tap-major interleave: 8 independent FMAs between accumulator reuses
        fma2(aIF0, wk0.x, s0); fma2(aOG0, wk0.y, s0);
        fma2(aIF1, wk0.x, s1); fma2(aOG1, wk0.y, s1);
        fma2(aIF2, wk0.x, s2); fma2(aOG2, wk0.y, s2);
        fma2(aIF3, wk0.x, s3); fma2(aOG3, wk0.y, s3);
        fma2(aIF0, wk1.x, s1); fma2(aOG0, wk1.y, s1);
        fma2(aIF1, wk1.x, s2); fma2(aOG1, wk1.y, s2);
        fma2(aIF2, wk1.x, s3); fma2(aOG2, wk1.y, s3);
        fma2(aIF3, wk1.x, s4); fma2(aOG3, wk1.y, s4);
    }

    float zi0, zf0, zi1, zf1, zi2, zf2, zi3, zf3;
    float zo0, zg0, zo1, zg1, zo2, zg2, zo3, zg3;
    unpack2(zi0, zf0, aIF0); unpack2(zi1, zf1, aIF1);
    unpack2(zi2, zf2, aIF2); unpack2(zi3, zf3, aIF3);
    unpack2(zo0, zg0, aOG0); unpack2(zo1, zg1, aOG1);
    unpack2(zo2, zg2, aOG2); unpack2(zo3, zg3, aOG3);

    // store gate-major: [row][b][j][g][w0..w0+3] (write-only -> bypass L1)
    size_t base = ((size_t)((row * BB + b) * HID + j)) * 4 * WW + w0;
    __stcg((float4*)&g_zbuf[base + 0 * WW], make_float4(zi0, zi1, zi2, zi3));
    __stcg((float4*)&g_zbuf[base + 1 * WW], make_float4(zf0, zf1, zf2, zf3));
    __stcg((float4*)&g_zbuf[base + 2 * WW], make_float4(zo0, zo1, zo2, zo3));
    __stcg((float4*)&g_zbuf[base + 3 * WW], make_float4(zg0, zg1, zg2, zg3));
}

// ---------------- persistent recurrence: all 64 rows in one kernel ----------------
// grid (8 jgroups, 16 b), 256 threads; thread tile: 1 j x 4 gates x 4 w
// Wh slice (96KB) preloaded to dynamic smem once -> inner loop is LDG-free.
// c lives in registers; h exchanged through L2 (stcg/ldcg) with a per-batch
// 8-CTA ticket barrier between rows; next row's z prefetched under the FMA loop.
__global__ __launch_bounds__(256) void steps_kernel(float* __restrict__ out) {
    const int jg = blockIdx.x, b = blockIdx.y;
    extern __shared__ __align__(16) float smem[];
    float (*hs)[68] = (float(*)[68])smem;                       // [HID][68]
    ulonglong2* ws = (ulonglong2*)(smem + SMEM_HS_FLOATS);      // [384][16] 16B each
    const int t = threadIdx.x;

    // h_{-1} = 0 (also sets pads, which stay zero forever)
    for (int i = t; i < HID * 68; i += 256) ((float*)hs)[i] = 0.0f;
    // preload this CTA's Wh slice: ws[ck*16 + tj] = g_Wh4[ck*HID + jg*16 + tj]
    {
        const float4* __restrict__ Wg4 = (const float4*)g_Wh;
        float4* wsf = (float4*)ws;
        for (int i = t; i < HID * 3 * 16; i += 256) {
            int ck = i >> 4, tjj = i & 15;
            wsf[i] = Wg4[ck * HID + jg * 16 + tjj];
        }
    }
    __syncthreads();

    const int tw = t & 15, tj = t >> 4;
    const int j = jg * 16 + tj;
    const int w0 = tw * 4;
    const int hbase = (b * HID + j) * WW + w0;
    const size_t zstride = (size_t)BB * HID * 4 * WW;          // per-row stride
    const float* zp = &g_zbuf[((size_t)(b * HID + j)) * 4 * WW + w0];

    float4 c4 = make_float4(0.0f, 0.0f, 0.0f, 0.0f);           // cell state in registers

    // z for row 0
    float4 qi = __ldcg((const float4*)&zp[0 * WW]);
    float4 qf = __ldcg((const float4*)&zp[1 * WW]);
    float4 qo = __ldcg((const float4*)&zp[2 * WW]);
    float4 qg = __ldcg((const float4*)&zp[3 * WW]);

    for (int row = 0; row < HH; row++) {
        // accumulators from prefetched z (bias already folded in)
        u64 aIF0 = pack2(qi.x, qf.x), aIF1 = pack2(qi.y, qf.y);
        u64 aIF2 = pack2(qi.z, qf.z), aIF3 = pack2(qi.w, qf.w);
        u64 aOG0 = pack2(qo.x, qg.x), aOG1 = pack2(qo.y, qg.y);
        u64 aOG2 = pack2(qo.z, qg.z), aOG3 = pack2(qo.w, qg.w);

        // prefetch z for next row: hidden under the 128-iteration FMA loop
        if (row + 1 < HH) {
            const float* znext = zp + (size_t)(row + 1) * zstride;
            qi = __ldcg((const float4*)&znext[0 * WW]);
            qf = __ldcg((const float4*)&znext[1 * WW]);
            qo = __ldcg((const float4*)&znext[2 * WW]);
            qg = __ldcg((const float4*)&znext[3 * WW]);
        }

#pragma unroll 4
        for (int cj = 0; cj < HID; cj++) {
            ulonglong2 wk0 = ws[(cj * 3 + 0) * 16 + tj];    // .x=(wi,wf), .y=(wo,wg)
            ulonglong2 wk1 = ws[(cj * 3 + 1) * 16 + tj];
            ulonglong2 wk2 = ws[(cj * 3 + 2) * 16 + tj];
            float4 v4 = *(const float4*)&hs[cj][w0];        // h[w0-1 .. w0+2]
            float  ve = hs[cj][w0 + 4];                     // h[w0+3]
            float  v5 = hs[cj][w0 + 5];                     // h[w0+4] (zero at right edge)
            u64 s0 = dup2(v4.x), s1 = dup2(v4.y), s2 = dup2(v4.z);
            u64 s3 = dup2(v4.w), s4 = dup2(ve),  s5 = dup2(v5);
            // tap-major interleave: 8 independent FMAs between accumulator reuses
            fma2(aIF0, wk0.x, s0); fma2(aOG0, wk0.y, s0);
            fma2(aIF1, wk0.x, s1); fma2(aOG1, wk0.y, s1);
            fma2(aIF2, wk0.x, s2); fma2(aOG2, wk0.y, s2);
            fma2(aIF3, wk0.x, s3); fma2(aOG3, wk0.y, s3);
            fma2(aIF0, wk1.x, s1); fma2(aOG0, wk1.y, s1);
            fma2(aIF1, wk1.x, s2); fma2(aOG1, wk1.y, s2);
            fma2(aIF2, wk1.x, s3); fma2(aOG2, wk1.y, s3);
            fma2(aIF3, wk1.x, s4); fma2(aOG3, wk1.y, s4);
            fma2(aIF0, wk2.x, s2); fma2(aOG0, wk2.y, s2);
            fma2(aIF1, wk2.x, s3); fma2(aOG1, wk2.y, s3);
            fma2(aIF2, wk2.x, s4); fma2(aOG2, wk2.y, s4);
            fma2(aIF3, wk2.x, s5); fma2(aOG3, wk2.y, s5);
        }

        float4 hnew;
        {
            float zi, zf, zo, zg;
            unpack2(zi, zf, aIF0); unpack2(zo, zg, aOG0);
            float ig = sigm(zi), fg = sigm(zf), og = sigm(zo), gg = tanh_f(zg);
            c4.x = fg * c4.x + ig * gg;  hnew.x = og * tanh_f(c4.x);
        }
        {
            float zi, zf, zo, zg;
            unpack2(zi, zf, aIF1); unpack2(zo, zg, aOG1);
            float ig = sigm(zi), fg = sigm(zf), og = sigm(zo), gg = tanh_f(zg);
            c4.y = fg * c4.y + ig * gg;  hnew.y = og * tanh_f(c4.y);
        }
        {
            float zi, zf, zo, zg;
            unpack2(zi, zf, aIF2); unpack2(zo, zg, aOG2);
            float ig = sigm(zi), fg = sigm(zf), og = sigm(zo), gg = tanh_f(zg);
            c4.z = fg * c4.z + ig * gg;  hnew.z = og * tanh_f(c4.z);
        }
        {
            float zi, zf, zo, zg;
            unpack2(zi, zf, aIF3); unpack2(zo, zg, aOG3);
            float ig = sigm(zi), fg = sigm(zf), og = sigm(zo), gg = tanh_f(zg);
            c4.w = fg * c4.w + ig * gg;  hnew.w = og * tanh_f(c4.w);
        }

        // publish h (L2, bypass L1) + final output (write-only -> bypass L1)
        float* hb = g_hbuf[row & 1];
        __stcg((float4*)&hb[hbase], hnew);
        __stcg((float4*)&out[((size_t)(b * HID + j) * HH + row) * WW + w0], hnew);

        if (row + 1 < HH) {
            // all 8 CTAs of this batch sync, then reload full h row into smem
            // (no barrier needed after the final row: nothing cross-CTA follows)
            batch_barrier(b, row + 1);

            // vectorized L2 read: 8 x LDG.128 per thread, all in flight at once
            const float4* __restrict__ hbr4 =
                (const float4*)&g_hbuf[row & 1][(size_t)b * HID * WW];
#pragma unroll 8
            for (int i = t; i < HID * (WW / 4); i += 256) {
                int cj = i >> 4, v = i & 15;             // 16 float4 per cj row
                float4 q = __ldcg(&hbr4[i]);
                float* d = &hs[cj][v * 4 + 1];
                d[0] = q.x; d[1] = q.y; d[2] = q.z; d[3] = q.w;
            }
            __syncthreads();
        }
    }
}

// ---------------- launch ----------------
extern "C" void kernel_launch(void* const* d_in, const int* in_sizes, int n_in,
                              void* d_out, int out_size) {
    // robust input identification by element count
    const float* x = nullptr;
    const float* w_is = nullptr;
    const float* b_is = nullptr;
    const float* w_ss = nullptr;
    const float* b_ss = nullptr;
    for (int i = 0; i < n_in; i++) {
        int sz = in_sizes[i];
        const float* p = (const float*)d_in[i];
        if (sz == BB * CIN * HH * WW)            x = p;       // 4,194,304
        else if (sz == 4 * HID * CIN * 3)        w_is = p;    // 98,304
        else if (sz == 4 * HID * HID * 3)        w_ss = p;    // 196,608
        else if (sz == 4 * HID) {                             // 512 (b_is first, b_ss second)
            if (!b_is) b_is = p; else b_ss = p;
        }
    }
    float* out = (float*)d_out;

    // allow 133KB dynamic smem for the persistent kernel (idempotent, non-stream API)
    cudaFuncSetAttribute(steps_kernel, cudaFuncAttributeMaxDynamicSharedMemorySize,
                         SMEM_STEPS_BYTES);

    prep_kernel<<<768, 256>>>(w_is, b_is, w_ss, b_ss);
    zis_kernel<<<dim3(8, BB, HH), 256>>>(x);
    steps_kernel<<<dim3(8, BB), 256, SMEM_STEPS_BYTES>>>(out);  // 128 CTAs, single wave
}